// round 5
// baseline (speedup 1.0000x reference)
#include <cuda_runtime.h>
#include <math.h>

// Problem constants
#define S_LEN  2048
#define DMODEL 1024
#define NH     16
#define DHEAD  64
#define BATCH  4
#define MROWS  (BATCH * S_LEN)      // 8192
#define QKV_N  (3 * NH * DHEAD)     // 3072

// Scratch (allocation-free rule: __device__ globals)
__device__ float g_qkv[MROWS * QKV_N];      // 8192 x 3072
__device__ float g_attn[MROWS * DMODEL];    // 8192 x 1024
__device__ float g_y[MROWS * DMODEL];       // 8192 x 1024

// ---------------- packed f32x2 helpers (Blackwell FFMA2 path) ----------------
__device__ __forceinline__ void fma2(unsigned long long &c, unsigned long long a,
                                     unsigned long long b) {
    asm("fma.rn.f32x2 %0, %1, %2, %0;" : "+l"(c) : "l"(a), "l"(b));
}
__device__ __forceinline__ unsigned long long mul2(unsigned long long a,
                                                   unsigned long long b) {
    unsigned long long r;
    asm("mul.rn.f32x2 %0, %1, %2;" : "=l"(r) : "l"(a), "l"(b));
    return r;
}
__device__ __forceinline__ unsigned long long pack2(float lo, float hi) {
    unsigned long long r;
    asm("mov.b64 %0, {%1, %2};" : "=l"(r) : "f"(lo), "f"(hi));
    return r;
}
__device__ __forceinline__ void unpack2(unsigned long long v, float &lo, float &hi) {
    asm("mov.b64 {%0, %1}, %2;" : "=f"(lo), "=f"(hi) : "l"(v));
}

// ---------------- GEMM: C[M,N] = A[M,K] @ B[N,K]^T (+bias) ----------------
// 128x128 tile, BK=16, 256 threads, 8x8 per-thread microtile, double-buffered smem.
// All M,N,K here are multiples of the tile sizes (8192/3072/1024) -> no guards.
__global__ void gemm_nt_kernel(const float* __restrict__ A, const float* __restrict__ B,
                               const float* __restrict__ bias, float* __restrict__ C,
                               int M, int N, int K)
{
    __shared__ float As[2][16][128];
    __shared__ float Bs[2][16][128];
    const int tid = threadIdx.x;
    const int tx = tid & 15, ty = tid >> 4;
    const int bm = blockIdx.y * 128, bn = blockIdx.x * 128;
    const int lr = tid >> 2;          // 0..63
    const int lk = (tid & 3) << 2;    // 0,4,8,12

    const float* Ap = A + (long long)(bm + lr) * K + lk;
    const float* Bp = B + (long long)(bn + lr) * K + lk;
    const long long str64 = (long long)64 * K;

    unsigned long long c2[8][4];
#pragma unroll
    for (int i = 0; i < 8; ++i)
#pragma unroll
        for (int j = 0; j < 4; ++j) c2[i][j] = 0ULL;

    float4 pa0 = *(const float4*)(Ap);
    float4 pa1 = *(const float4*)(Ap + str64);
    float4 pb0 = *(const float4*)(Bp);
    float4 pb1 = *(const float4*)(Bp + str64);
    As[0][lk+0][lr] = pa0.x; As[0][lk+1][lr] = pa0.y; As[0][lk+2][lr] = pa0.z; As[0][lk+3][lr] = pa0.w;
    As[0][lk+0][lr+64] = pa1.x; As[0][lk+1][lr+64] = pa1.y; As[0][lk+2][lr+64] = pa1.z; As[0][lk+3][lr+64] = pa1.w;
    Bs[0][lk+0][lr] = pb0.x; Bs[0][lk+1][lr] = pb0.y; Bs[0][lk+2][lr] = pb0.z; Bs[0][lk+3][lr] = pb0.w;
    Bs[0][lk+0][lr+64] = pb1.x; Bs[0][lk+1][lr+64] = pb1.y; Bs[0][lk+2][lr+64] = pb1.z; Bs[0][lk+3][lr+64] = pb1.w;
    __syncthreads();

    const int nt = K >> 4;
    for (int t = 0; t < nt; ++t) {
        const int cur = t & 1;
        if (t + 1 < nt) {
            const float* Ax = Ap + (t + 1) * 16;
            const float* Bx = Bp + (t + 1) * 16;
            pa0 = *(const float4*)(Ax); pa1 = *(const float4*)(Ax + str64);
            pb0 = *(const float4*)(Bx); pb1 = *(const float4*)(Bx + str64);
        }
#pragma unroll
        for (int kk = 0; kk < 16; ++kk) {
            float4 av0 = *(const float4*)&As[cur][kk][ty * 8];
            float4 av1 = *(const float4*)&As[cur][kk][ty * 8 + 4];
            float4 bv0 = *(const float4*)&Bs[cur][kk][tx * 8];
            float4 bv1 = *(const float4*)&Bs[cur][kk][tx * 8 + 4];
            unsigned long long bb0 = pack2(bv0.x, bv0.y);
            unsigned long long bb1 = pack2(bv0.z, bv0.w);
            unsigned long long bb2 = pack2(bv1.x, bv1.y);
            unsigned long long bb3 = pack2(bv1.z, bv1.w);
            float aa[8] = {av0.x, av0.y, av0.z, av0.w, av1.x, av1.y, av1.z, av1.w};
#pragma unroll
            for (int i = 0; i < 8; ++i) {
                unsigned long long a2 = pack2(aa[i], aa[i]);
                fma2(c2[i][0], a2, bb0);
                fma2(c2[i][1], a2, bb1);
                fma2(c2[i][2], a2, bb2);
                fma2(c2[i][3], a2, bb3);
            }
        }
        if (t + 1 < nt) {
            const int nx = cur ^ 1;
            As[nx][lk+0][lr] = pa0.x; As[nx][lk+1][lr] = pa0.y; As[nx][lk+2][lr] = pa0.z; As[nx][lk+3][lr] = pa0.w;
            As[nx][lk+0][lr+64] = pa1.x; As[nx][lk+1][lr+64] = pa1.y; As[nx][lk+2][lr+64] = pa1.z; As[nx][lk+3][lr+64] = pa1.w;
            Bs[nx][lk+0][lr] = pb0.x; Bs[nx][lk+1][lr] = pb0.y; Bs[nx][lk+2][lr] = pb0.z; Bs[nx][lk+3][lr] = pb0.w;
            Bs[nx][lk+0][lr+64] = pb1.x; Bs[nx][lk+1][lr+64] = pb1.y; Bs[nx][lk+2][lr+64] = pb1.z; Bs[nx][lk+3][lr+64] = pb1.w;
        }
        __syncthreads();
    }

#pragma unroll
    for (int i = 0; i < 8; ++i) {
        const int row = bm + ty * 8 + i;
        const int col = bn + tx * 8;
        float o[8];
        unpack2(c2[i][0], o[0], o[1]); unpack2(c2[i][1], o[2], o[3]);
        unpack2(c2[i][2], o[4], o[5]); unpack2(c2[i][3], o[6], o[7]);
        if (bias) {
#pragma unroll
            for (int j = 0; j < 8; ++j) o[j] += bias[col + j];
        }
        *(float4*)(C + (long long)row * N + col)     = make_float4(o[0], o[1], o[2], o[3]);
        *(float4*)(C + (long long)row * N + col + 4) = make_float4(o[4], o[5], o[6], o[7]);
    }
}

// ---------------- Flash attention ----------------
// Grid (S/128, H, B), 256 threads. BQ=128 q-rows per CTA, BKV=64 keys/iter.
// Thread (tx,ty)=(tid&15,tid>>4): rows ty*8..+7; score cols tx+16j; O cols tx*4..+3.
#define ATTN_SMEM ((128*64 + 64*65 + 64*64 + 128*64) * 4)   // 98560 B

__global__ void attn_kernel(const float* __restrict__ qkv, const int* __restrict__ amask,
                            float* __restrict__ outp)
{
    extern __shared__ float sm[];
    float* Qs = sm;                 // [128][64] natural
    float* Ks = Qs + 128 * 64;      // [64][65]  padded stride -> conflict-free scalar reads
    float* Vs = Ks + 64 * 65;       // [64][64]  natural
    float* Ps = Vs + 64 * 64;       // [128][64] natural

    const int tid = threadIdx.x;
    const int tx = tid & 15, ty = tid >> 4;
    const int q0 = blockIdx.x * 128;
    const int h  = blockIdx.y;
    const int b  = blockIdx.z;

    const float* qbase = qkv + ((long long)(b * S_LEN + q0)) * QKV_N + h * DHEAD;
    const float* kbase = qkv + ((long long)(b * S_LEN)) * QKV_N + NH * DHEAD + h * DHEAD;
    const float* vbase = kbase + NH * DHEAD;
    const int* mrow = amask + b * S_LEN;

    // Load Q tile (pre-scaled by 1/sqrt(DH)=0.125)
#pragma unroll
    for (int it = 0; it < 8; ++it) {
        int r = ty + it * 16;
        int d4 = tx * 4;
        float4 v = *(const float4*)(qbase + (long long)r * QKV_N + d4);
        v.x *= 0.125f; v.y *= 0.125f; v.z *= 0.125f; v.w *= 0.125f;
        *(float4*)&Qs[r * 64 + d4] = v;
    }

    float m[8], l[8];
    unsigned long long O2[8][2];
#pragma unroll
    for (int i = 0; i < 8; ++i) { m[i] = -1e30f; l[i] = 0.f; O2[i][0] = 0ULL; O2[i][1] = 0ULL; }

    for (int kt = 0; kt < S_LEN / 64; ++kt) {
        __syncthreads();   // prior iteration's consumers of Ks/Vs/Ps done (also orders Q load)
        // Load K (natural rows, stride 65 -> conflict-free scalar reads) and V tiles
#pragma unroll
        for (int it = 0; it < 4; ++it) {
            int r = ty + it * 16;
            int d4 = tx * 4;
            float4 kv = *(const float4*)(kbase + (long long)(kt * 64 + r) * QKV_N + d4);
            Ks[r * 65 + d4 + 0] = kv.x; Ks[r * 65 + d4 + 1] = kv.y;
            Ks[r * 65 + d4 + 2] = kv.z; Ks[r * 65 + d4 + 3] = kv.w;
            float4 vv = *(const float4*)(vbase + (long long)(kt * 64 + r) * QKV_N + d4);
            *(float4*)&Vs[r * 64 + d4] = vv;
        }
        __syncthreads();

        // S = Q @ K^T  (f32x2, pairs over key-cols)
        unsigned long long s2[8][2];
#pragma unroll
        for (int i = 0; i < 8; ++i) { s2[i][0] = 0ULL; s2[i][1] = 0ULL; }
#pragma unroll
        for (int d = 0; d < 64; d += 4) {
            unsigned long long bb[4][2];
#pragma unroll
            for (int u = 0; u < 4; ++u) {
                float b0 = Ks[(tx     ) * 65 + d + u];
                float b1 = Ks[(tx + 16) * 65 + d + u];
                float b2 = Ks[(tx + 32) * 65 + d + u];
                float b3 = Ks[(tx + 48) * 65 + d + u];
                bb[u][0] = pack2(b0, b1);
                bb[u][1] = pack2(b2, b3);
            }
#pragma unroll
            for (int i = 0; i < 8; ++i) {
                float4 a = *(const float4*)&Qs[(ty * 8 + i) * 64 + d];
                unsigned long long a2;
                a2 = pack2(a.x, a.x); fma2(s2[i][0], a2, bb[0][0]); fma2(s2[i][1], a2, bb[0][1]);
                a2 = pack2(a.y, a.y); fma2(s2[i][0], a2, bb[1][0]); fma2(s2[i][1], a2, bb[1][1]);
                a2 = pack2(a.z, a.z); fma2(s2[i][0], a2, bb[2][0]); fma2(s2[i][1], a2, bb[2][1]);
                a2 = pack2(a.w, a.w); fma2(s2[i][0], a2, bb[3][0]); fma2(s2[i][1], a2, bb[3][1]);
            }
        }

        // Key-padding mask + online softmax.
        // Robustness: p is zeroed EXPLICITLY under the mask predicate (not via
        // sentinel underflow) so an all-masked leading tile contributes exactly 0.
        const int kidx = kt * 64;
        const int mk0 = mrow[kidx + tx];
        const int mk1 = mrow[kidx + tx + 16];
        const int mk2 = mrow[kidx + tx + 32];
        const int mk3 = mrow[kidx + tx + 48];
#pragma unroll
        for (int i = 0; i < 8; ++i) {
            float sv0, sv1, sv2, sv3;
            unpack2(s2[i][0], sv0, sv1);
            unpack2(s2[i][1], sv2, sv3);
            if (mk0) sv0 = -1e30f;
            if (mk1) sv1 = -1e30f;
            if (mk2) sv2 = -1e30f;
            if (mk3) sv3 = -1e30f;
            float tm = fmaxf(fmaxf(sv0, sv1), fmaxf(sv2, sv3));
#pragma unroll
            for (int off = 1; off < 16; off <<= 1)
                tm = fmaxf(tm, __shfl_xor_sync(0xffffffffu, tm, off));
            float mnew = fmaxf(m[i], tm);
            float corr = __expf(m[i] - mnew);
            float p0 = mk0 ? 0.f : __expf(sv0 - mnew);
            float p1 = mk1 ? 0.f : __expf(sv1 - mnew);
            float p2 = mk2 ? 0.f : __expf(sv2 - mnew);
            float p3 = mk3 ? 0.f : __expf(sv3 - mnew);
            float rs = p0 + p1 + p2 + p3;
#pragma unroll
            for (int off = 1; off < 16; off <<= 1)
                rs += __shfl_xor_sync(0xffffffffu, rs, off);
            l[i] = l[i] * corr + rs;
            m[i] = mnew;
            unsigned long long cc = pack2(corr, corr);
            O2[i][0] = mul2(O2[i][0], cc);
            O2[i][1] = mul2(O2[i][1], cc);
            const int pr = (ty * 8 + i) * 64;
            Ps[pr + tx]      = p0;
            Ps[pr + tx + 16] = p1;
            Ps[pr + tx + 32] = p2;
            Ps[pr + tx + 48] = p3;
        }
        __syncthreads();   // Ps fully written (read across tx groups below)

        // O += P @ V  (f32x2, pairs over head-dim cols)
#pragma unroll
        for (int k = 0; k < 64; k += 4) {
            unsigned long long vb[4][2];
#pragma unroll
            for (int u = 0; u < 4; ++u) {
                float4 vv = *(const float4*)&Vs[(k + u) * 64 + tx * 4];
                vb[u][0] = pack2(vv.x, vv.y);
                vb[u][1] = pack2(vv.z, vv.w);
            }
#pragma unroll
            for (int i = 0; i < 8; ++i) {
                float4 a = *(const float4*)&Ps[(ty * 8 + i) * 64 + k];
                unsigned long long a2;
                a2 = pack2(a.x, a.x); fma2(O2[i][0], a2, vb[0][0]); fma2(O2[i][1], a2, vb[0][1]);
                a2 = pack2(a.y, a.y); fma2(O2[i][0], a2, vb[1][0]); fma2(O2[i][1], a2, vb[1][1]);
                a2 = pack2(a.z, a.z); fma2(O2[i][0], a2, vb[2][0]); fma2(O2[i][1], a2, vb[2][1]);
                a2 = pack2(a.w, a.w); fma2(O2[i][0], a2, vb[3][0]); fma2(O2[i][1], a2, vb[3][1]);
            }
        }
    }

    // Normalize and write attn output [row][h*64 + d]
#pragma unroll
    for (int i = 0; i < 8; ++i) {
        float inv = 1.0f / l[i];
        float o0, o1, o2, o3;
        unpack2(O2[i][0], o0, o1);
        unpack2(O2[i][1], o2, o3);
        long long row = (long long)(b * S_LEN + q0 + ty * 8 + i);
        *(float4*)(outp + row * DMODEL + h * DHEAD + tx * 4) =
            make_float4(o0 * inv, o1 * inv, o2 * inv, o3 * inv);
    }
}

// ---------------- Residual + LayerNorm ----------------
// One 256-thread block per row; 4 elems/thread.
__global__ void ln_kernel(const float* __restrict__ x0, const float* __restrict__ y,
                          const float* __restrict__ gamma, const float* __restrict__ beta,
                          float* __restrict__ outp)
{
    const int row = blockIdx.x;
    const int tid = threadIdx.x;
    const long long base = (long long)row * DMODEL;
    float4 xv = *(const float4*)(x0 + base + tid * 4);
    float4 yv = *(const float4*)(y + base + tid * 4);
    float v0 = xv.x + yv.x, v1 = xv.y + yv.y, v2 = xv.z + yv.z, v3 = xv.w + yv.w;
    float s = v0 + v1 + v2 + v3;
    float q = v0 * v0 + v1 * v1 + v2 * v2 + v3 * v3;
#pragma unroll
    for (int off = 16; off > 0; off >>= 1) {
        s += __shfl_xor_sync(0xffffffffu, s, off);
        q += __shfl_xor_sync(0xffffffffu, q, off);
    }
    __shared__ float reds[8], redq[8];
    const int wid = tid >> 5, lane = tid & 31;
    if (lane == 0) { reds[wid] = s; redq[wid] = q; }
    __syncthreads();
    float ts = 0.f, tq = 0.f;
#pragma unroll
    for (int w = 0; w < 8; ++w) { ts += reds[w]; tq += redq[w]; }
    const float mu   = ts * (1.0f / DMODEL);
    const float var  = tq * (1.0f / DMODEL) - mu * mu;
    const float rstd = rsqrtf(var + 1e-5f);
    float4 gv = *(const float4*)(gamma + tid * 4);
    float4 bv = *(const float4*)(beta + tid * 4);
    float4 o;
    o.x = (v0 - mu) * rstd * gv.x + bv.x;
    o.y = (v1 - mu) * rstd * gv.y + bv.y;
    o.z = (v2 - mu) * rstd * gv.z + bv.z;
    o.w = (v3 - mu) * rstd * gv.w + bv.w;
    *(float4*)(outp + base + tid * 4) = o;
}

// ---------------- launch ----------------
extern "C" void kernel_launch(void* const* d_in, const int* in_sizes, int n_in,
                              void* d_out, int out_size)
{
    const float* inp   = (const float*)d_in[0];
    const int*   amask = (const int*)  d_in[1];
    const float* Wqkv  = (const float*)d_in[2];
    const float* bqkv  = (const float*)d_in[3];
    const float* Wo    = (const float*)d_in[4];
    const float* gamma = (const float*)d_in[5];
    const float* beta  = (const float*)d_in[6];
    float* outp = (float*)d_out;

    float *qkv = nullptr, *attn = nullptr, *yb = nullptr;
    cudaGetSymbolAddress((void**)&qkv,  g_qkv);
    cudaGetSymbolAddress((void**)&attn, g_attn);
    cudaGetSymbolAddress((void**)&yb,   g_y);

    cudaFuncSetAttribute(attn_kernel, cudaFuncAttributeMaxDynamicSharedMemorySize, ATTN_SMEM);

    dim3 blk(256);
    dim3 g1(QKV_N / 128, MROWS / 128);
    gemm_nt_kernel<<<g1, blk>>>(inp, Wqkv, bqkv, qkv, MROWS, QKV_N, DMODEL);

    dim3 g2(S_LEN / 128, NH, BATCH);
    attn_kernel<<<g2, blk, ATTN_SMEM>>>(qkv, amask, attn);

    dim3 g3(DMODEL / 128, MROWS / 128);
    gemm_nt_kernel<<<g3, blk>>>(attn, Wo, nullptr, yb, MROWS, DMODEL, DMODEL);

    ln_kernel<<<MROWS, blk>>>(inp, yb, gamma, beta, outp);
}

// round 11
// speedup vs baseline: 1.4385x; 1.4385x over previous
#include <cuda_runtime.h>
#include <math.h>

// Problem constants
#define S_LEN  2048
#define DMODEL 1024
#define NH     16
#define DHEAD  64
#define BATCH  4
#define MROWS  (BATCH * S_LEN)      // 8192
#define QKV_N  (3 * NH * DHEAD)     // 3072

// Scratch (allocation-free rule: __device__ globals)
__device__ float g_qkv[MROWS * QKV_N];      // 8192 x 3072
__device__ float g_attn[MROWS * DMODEL];    // 8192 x 1024
__device__ float g_y[MROWS * DMODEL];       // 8192 x 1024

// ---------------- packed f32x2 helpers (Blackwell FFMA2 path) ----------------
__device__ __forceinline__ void fma2(unsigned long long &c, unsigned long long a,
                                     unsigned long long b) {
    asm("fma.rn.f32x2 %0, %1, %2, %0;" : "+l"(c) : "l"(a), "l"(b));
}
__device__ __forceinline__ unsigned long long mul2(unsigned long long a,
                                                   unsigned long long b) {
    unsigned long long r;
    asm("mul.rn.f32x2 %0, %1, %2;" : "=l"(r) : "l"(a), "l"(b));
    return r;
}
__device__ __forceinline__ unsigned long long pack2(float lo, float hi) {
    unsigned long long r;
    asm("mov.b64 %0, {%1, %2};" : "=l"(r) : "f"(lo), "f"(hi));
    return r;
}
__device__ __forceinline__ void unpack2(unsigned long long v, float &lo, float &hi) {
    asm("mov.b64 {%0, %1}, %2;" : "=f"(lo), "=f"(hi) : "l"(v));
}

// ---------------- tf32 helpers ----------------
__device__ __forceinline__ unsigned int f2tf32(float x) {
    unsigned int r;
    asm("cvt.rna.tf32.f32 %0, %1;" : "=r"(r) : "f"(x));
    return r;
}
__device__ __forceinline__ void mma_tf32(float c[4], const unsigned int a[4],
                                         const unsigned int b[2]) {
    asm("mma.sync.aligned.m16n8k8.row.col.f32.tf32.tf32.f32 "
        "{%0,%1,%2,%3}, {%4,%5,%6,%7}, {%8,%9}, {%0,%1,%2,%3};"
        : "+f"(c[0]), "+f"(c[1]), "+f"(c[2]), "+f"(c[3])
        : "r"(a[0]), "r"(a[1]), "r"(a[2]), "r"(a[3]), "r"(b[0]), "r"(b[1]));
}
// Convert a float4 to tf32 bit-patterns packed in uint4 (applied ONCE at smem store).
__device__ __forceinline__ uint4 cvt4_tf32(float4 v) {
    uint4 r;
    r.x = f2tf32(v.x); r.y = f2tf32(v.y); r.z = f2tf32(v.z); r.w = f2tf32(v.w);
    return r;
}

// ---------------- GEMM (tf32 tensor cores): C[M,N] = A[M,K] @ B[N,K]^T (+bias) ----
// 128x128 CTA tile, BK=16, 256 threads = 8 warps as 2(m)x4(n); each warp 64x32
// via 4x4 grid of m16n8k8 tf32 mma.
// Smem m-major [row][k], stride GK=20 uints:
//   fragment load bank = (20*qr + qc + const) mod 32; 20*qr mod 32 =
//   {0,20,8,28,16,4,24,12} (distinct multiples of 4), +qc(0..3) -> all 32 banks,
//   conflict-free. Loader keeps coalesced mapping (lr=tid>>2, lk=(tid&3)*4):
//   64B-coalesced gmem rows, 16B-aligned uint4 smem stores.
// tf32 conversion applied ONCE at store (loader), not per fragment load:
//   removes 24 redundant cvt per warp per ks-step from the LDS->HMMA critical path.
#define GK 20   // padded k-stride (uints); 20*4=80B, 16B-aligned per row

__global__ void gemm_nt_kernel(const float* __restrict__ A, const float* __restrict__ B,
                               const float* __restrict__ bias, float* __restrict__ C,
                               int M, int N, int K)
{
    __shared__ unsigned int As[2][128][GK];
    __shared__ unsigned int Bs[2][128][GK];
    const int tid = threadIdx.x;
    const int bm = blockIdx.y * 128, bn = blockIdx.x * 128;
    const int lr = tid >> 2;          // 0..63  (loader row)
    const int lk = (tid & 3) << 2;    // 0,4,8,12 (loader k)

    const int wid = tid >> 5;
    const int lane = tid & 31;
    const int warp_m = (wid & 1) * 64;   // 0 or 64
    const int warp_n = (wid >> 1) * 32;  // 0,32,64,96
    const int qr = lane >> 2;            // 0..7
    const int qc = lane & 3;             // 0..3

    const float* Ap = A + (long long)(bm + lr) * K + lk;
    const float* Bp = B + (long long)(bn + lr) * K + lk;
    const long long str64 = (long long)64 * K;

    float c[4][4][4];   // [mt][nt][reg]
#pragma unroll
    for (int i = 0; i < 4; ++i)
#pragma unroll
        for (int j = 0; j < 4; ++j)
#pragma unroll
            for (int r = 0; r < 4; ++r) c[i][j][r] = 0.f;

    float4 pa0 = *(const float4*)(Ap);
    float4 pa1 = *(const float4*)(Ap + str64);
    float4 pb0 = *(const float4*)(Bp);
    float4 pb1 = *(const float4*)(Bp + str64);
    *(uint4*)&As[0][lr][lk]      = cvt4_tf32(pa0);
    *(uint4*)&As[0][lr + 64][lk] = cvt4_tf32(pa1);
    *(uint4*)&Bs[0][lr][lk]      = cvt4_tf32(pb0);
    *(uint4*)&Bs[0][lr + 64][lk] = cvt4_tf32(pb1);
    __syncthreads();

    const int nt_iters = K >> 4;
    for (int t = 0; t < nt_iters; ++t) {
        const int cur = t & 1;
        if (t + 1 < nt_iters) {
            const float* Ax = Ap + (t + 1) * 16;
            const float* Bx = Bp + (t + 1) * 16;
            pa0 = *(const float4*)(Ax); pa1 = *(const float4*)(Ax + str64);
            pb0 = *(const float4*)(Bx); pb1 = *(const float4*)(Bx + str64);
        }
#pragma unroll
        for (int ks = 0; ks < 2; ++ks) {
            const int k0 = ks * 8;
            // A fragment (m16k8 row-major): a0:(qr,qc) a1:(qr+8,qc) a2:(qr,qc+4) a3:(qr+8,qc+4)
            unsigned int af[4][4];
#pragma unroll
            for (int mt = 0; mt < 4; ++mt) {
                const int row0 = warp_m + mt * 16 + qr;
                af[mt][0] = As[cur][row0    ][k0 + qc];
                af[mt][1] = As[cur][row0 + 8][k0 + qc];
                af[mt][2] = As[cur][row0    ][k0 + qc + 4];
                af[mt][3] = As[cur][row0 + 8][k0 + qc + 4];
            }
            // B fragment (k8n8 col-major): b0:(k=qc,n=qr) b1:(k=qc+4,n=qr)
            unsigned int bf[4][2];
#pragma unroll
            for (int ntile = 0; ntile < 4; ++ntile) {
                const int col0 = warp_n + ntile * 8 + qr;
                bf[ntile][0] = Bs[cur][col0][k0 + qc];
                bf[ntile][1] = Bs[cur][col0][k0 + qc + 4];
            }
#pragma unroll
            for (int mt = 0; mt < 4; ++mt)
#pragma unroll
                for (int ntile = 0; ntile < 4; ++ntile)
                    mma_tf32(c[mt][ntile], af[mt], bf[ntile]);
        }
        if (t + 1 < nt_iters) {
            const int nx = cur ^ 1;
            *(uint4*)&As[nx][lr][lk]      = cvt4_tf32(pa0);
            *(uint4*)&As[nx][lr + 64][lk] = cvt4_tf32(pa1);
            *(uint4*)&Bs[nx][lr][lk]      = cvt4_tf32(pb0);
            *(uint4*)&Bs[nx][lr + 64][lk] = cvt4_tf32(pb1);
        }
        __syncthreads();
    }

    // Epilogue: C fragment (m16n8): c0:(qr,2qc) c1:(qr,2qc+1) c2:(qr+8,2qc) c3:(qr+8,2qc+1)
#pragma unroll
    for (int mt = 0; mt < 4; ++mt) {
#pragma unroll
        for (int ntile = 0; ntile < 4; ++ntile) {
            const int row = bm + warp_m + mt * 16 + qr;
            const int col = bn + warp_n + ntile * 8 + 2 * qc;
            float b0 = 0.f, b1 = 0.f;
            if (bias) { b0 = bias[col]; b1 = bias[col + 1]; }
            float2 lo = make_float2(c[mt][ntile][0] + b0, c[mt][ntile][1] + b1);
            float2 hi = make_float2(c[mt][ntile][2] + b0, c[mt][ntile][3] + b1);
            *(float2*)(C + (long long)row * N + col)       = lo;
            *(float2*)(C + (long long)(row + 8) * N + col) = hi;
        }
    }
}

// ---------------- Flash attention (unchanged fp32/FFMA2; proven in R5) ----------
// Grid (S/128, H, B), 256 threads. BQ=128 q-rows per CTA, BKV=64 keys/iter.
#define ATTN_SMEM ((128*64 + 64*65 + 64*64 + 128*64) * 4)   // 98560 B

__global__ void attn_kernel(const float* __restrict__ qkv, const int* __restrict__ amask,
                            float* __restrict__ outp)
{
    extern __shared__ float sm[];
    float* Qs = sm;                 // [128][64] natural
    float* Ks = Qs + 128 * 64;      // [64][65]  padded stride -> conflict-free scalar reads
    float* Vs = Ks + 64 * 65;       // [64][64]  natural
    float* Ps = Vs + 64 * 64;       // [128][64] natural

    const int tid = threadIdx.x;
    const int tx = tid & 15, ty = tid >> 4;
    const int q0 = blockIdx.x * 128;
    const int h  = blockIdx.y;
    const int b  = blockIdx.z;

    const float* qbase = qkv + ((long long)(b * S_LEN + q0)) * QKV_N + h * DHEAD;
    const float* kbase = qkv + ((long long)(b * S_LEN)) * QKV_N + NH * DHEAD + h * DHEAD;
    const float* vbase = kbase + NH * DHEAD;
    const int* mrow = amask + b * S_LEN;

    // Load Q tile (pre-scaled by 1/sqrt(DH)=0.125)
#pragma unroll
    for (int it = 0; it < 8; ++it) {
        int r = ty + it * 16;
        int d4 = tx * 4;
        float4 v = *(const float4*)(qbase + (long long)r * QKV_N + d4);
        v.x *= 0.125f; v.y *= 0.125f; v.z *= 0.125f; v.w *= 0.125f;
        *(float4*)&Qs[r * 64 + d4] = v;
    }

    float m[8], l[8];
    unsigned long long O2[8][2];
#pragma unroll
    for (int i = 0; i < 8; ++i) { m[i] = -1e30f; l[i] = 0.f; O2[i][0] = 0ULL; O2[i][1] = 0ULL; }

    for (int kt = 0; kt < S_LEN / 64; ++kt) {
        __syncthreads();   // prior iteration's consumers of Ks/Vs/Ps done (also orders Q load)
#pragma unroll
        for (int it = 0; it < 4; ++it) {
            int r = ty + it * 16;
            int d4 = tx * 4;
            float4 kv = *(const float4*)(kbase + (long long)(kt * 64 + r) * QKV_N + d4);
            Ks[r * 65 + d4 + 0] = kv.x; Ks[r * 65 + d4 + 1] = kv.y;
            Ks[r * 65 + d4 + 2] = kv.z; Ks[r * 65 + d4 + 3] = kv.w;
            float4 vv = *(const float4*)(vbase + (long long)(kt * 64 + r) * QKV_N + d4);
            *(float4*)&Vs[r * 64 + d4] = vv;
        }
        __syncthreads();

        // S = Q @ K^T  (f32x2, pairs over key-cols)
        unsigned long long s2[8][2];
#pragma unroll
        for (int i = 0; i < 8; ++i) { s2[i][0] = 0ULL; s2[i][1] = 0ULL; }
#pragma unroll
        for (int d = 0; d < 64; d += 4) {
            unsigned long long bb[4][2];
#pragma unroll
            for (int u = 0; u < 4; ++u) {
                float b0 = Ks[(tx     ) * 65 + d + u];
                float b1 = Ks[(tx + 16) * 65 + d + u];
                float b2 = Ks[(tx + 32) * 65 + d + u];
                float b3 = Ks[(tx + 48) * 65 + d + u];
                bb[u][0] = pack2(b0, b1);
                bb[u][1] = pack2(b2, b3);
            }
#pragma unroll
            for (int i = 0; i < 8; ++i) {
                float4 a = *(const float4*)&Qs[(ty * 8 + i) * 64 + d];
                unsigned long long a2;
                a2 = pack2(a.x, a.x); fma2(s2[i][0], a2, bb[0][0]); fma2(s2[i][1], a2, bb[0][1]);
                a2 = pack2(a.y, a.y); fma2(s2[i][0], a2, bb[1][0]); fma2(s2[i][1], a2, bb[1][1]);
                a2 = pack2(a.z, a.z); fma2(s2[i][0], a2, bb[2][0]); fma2(s2[i][1], a2, bb[2][1]);
                a2 = pack2(a.w, a.w); fma2(s2[i][0], a2, bb[3][0]); fma2(s2[i][1], a2, bb[3][1]);
            }
        }

        // Key-padding mask + online softmax (explicit mask-predicate zeroing).
        const int kidx = kt * 64;
        const int mk0 = mrow[kidx + tx];
        const int mk1 = mrow[kidx + tx + 16];
        const int mk2 = mrow[kidx + tx + 32];
        const int mk3 = mrow[kidx + tx + 48];
#pragma unroll
        for (int i = 0; i < 8; ++i) {
            float sv0, sv1, sv2, sv3;
            unpack2(s2[i][0], sv0, sv1);
            unpack2(s2[i][1], sv2, sv3);
            if (mk0) sv0 = -1e30f;
            if (mk1) sv1 = -1e30f;
            if (mk2) sv2 = -1e30f;
            if (mk3) sv3 = -1e30f;
            float tm = fmaxf(fmaxf(sv0, sv1), fmaxf(sv2, sv3));
#pragma unroll
            for (int off = 1; off < 16; off <<= 1)
                tm = fmaxf(tm, __shfl_xor_sync(0xffffffffu, tm, off));
            float mnew = fmaxf(m[i], tm);
            float corr = __expf(m[i] - mnew);
            float p0 = mk0 ? 0.f : __expf(sv0 - mnew);
            float p1 = mk1 ? 0.f : __expf(sv1 - mnew);
            float p2 = mk2 ? 0.f : __expf(sv2 - mnew);
            float p3 = mk3 ? 0.f : __expf(sv3 - mnew);
            float rs = p0 + p1 + p2 + p3;
#pragma unroll
            for (int off = 1; off < 16; off <<= 1)
                rs += __shfl_xor_sync(0xffffffffu, rs, off);
            l[i] = l[i] * corr + rs;
            m[i] = mnew;
            unsigned long long cc = pack2(corr, corr);
            O2[i][0] = mul2(O2[i][0], cc);
            O2[i][1] = mul2(O2[i][1], cc);
            const int pr = (ty * 8 + i) * 64;
            Ps[pr + tx]      = p0;
            Ps[pr + tx + 16] = p1;
            Ps[pr + tx + 32] = p2;
            Ps[pr + tx + 48] = p3;
        }
        __syncthreads();   // Ps fully written (read across tx groups below)

        // O += P @ V  (f32x2, pairs over head-dim cols)
#pragma unroll
        for (int k = 0; k < 64; k += 4) {
            unsigned long long vb[4][2];
#pragma unroll
            for (int u = 0; u < 4; ++u) {
                float4 vv = *(const float4*)&Vs[(k + u) * 64 + tx * 4];
                vb[u][0] = pack2(vv.x, vv.y);
                vb[u][1] = pack2(vv.z, vv.w);
            }
#pragma unroll
            for (int i = 0; i < 8; ++i) {
                float4 a = *(const float4*)&Ps[(ty * 8 + i) * 64 + k];
                unsigned long long a2;
                a2 = pack2(a.x, a.x); fma2(O2[i][0], a2, vb[0][0]); fma2(O2[i][1], a2, vb[0][1]);
                a2 = pack2(a.y, a.y); fma2(O2[i][0], a2, vb[1][0]); fma2(O2[i][1], a2, vb[1][1]);
                a2 = pack2(a.z, a.z); fma2(O2[i][0], a2, vb[2][0]); fma2(O2[i][1], a2, vb[2][1]);
                a2 = pack2(a.w, a.w); fma2(O2[i][0], a2, vb[3][0]); fma2(O2[i][1], a2, vb[3][1]);
            }
        }
    }

    // Normalize and write attn output [row][h*64 + d]
#pragma unroll
    for (int i = 0; i < 8; ++i) {
        float inv = 1.0f / l[i];
        float o0, o1, o2, o3;
        unpack2(O2[i][0], o0, o1);
        unpack2(O2[i][1], o2, o3);
        long long row = (long long)(b * S_LEN + q0 + ty * 8 + i);
        *(float4*)(outp + row * DMODEL + h * DHEAD + tx * 4) =
            make_float4(o0 * inv, o1 * inv, o2 * inv, o3 * inv);
    }
}

// ---------------- Residual + LayerNorm ----------------
__global__ void ln_kernel(const float* __restrict__ x0, const float* __restrict__ y,
                          const float* __restrict__ gamma, const float* __restrict__ beta,
                          float* __restrict__ outp)
{
    const int row = blockIdx.x;
    const int tid = threadIdx.x;
    const long long base = (long long)row * DMODEL;
    float4 xv = *(const float4*)(x0 + base + tid * 4);
    float4 yv = *(const float4*)(y + base + tid * 4);
    float v0 = xv.x + yv.x, v1 = xv.y + yv.y, v2 = xv.z + yv.z, v3 = xv.w + yv.w;
    float s = v0 + v1 + v2 + v3;
    float q = v0 * v0 + v1 * v1 + v2 * v2 + v3 * v3;
#pragma unroll
    for (int off = 16; off > 0; off >>= 1) {
        s += __shfl_xor_sync(0xffffffffu, s, off);
        q += __shfl_xor_sync(0xffffffffu, q, off);
    }
    __shared__ float reds[8], redq[8];
    const int wid = tid >> 5, lane = tid & 31;
    if (lane == 0) { reds[wid] = s; redq[wid] = q; }
    __syncthreads();
    float ts = 0.f, tq = 0.f;
#pragma unroll
    for (int w = 0; w < 8; ++w) { ts += reds[w]; tq += redq[w]; }
    const float mu   = ts * (1.0f / DMODEL);
    const float var  = tq * (1.0f / DMODEL) - mu * mu;
    const float rstd = rsqrtf(var + 1e-5f);
    float4 gv = *(const float4*)(gamma + tid * 4);
    float4 bv = *(const float4*)(beta + tid * 4);
    float4 o;
    o.x = (v0 - mu) * rstd * gv.x + bv.x;
    o.y = (v1 - mu) * rstd * gv.y + bv.y;
    o.z = (v2 - mu) * rstd * gv.z + bv.z;
    o.w = (v3 - mu) * rstd * gv.w + bv.w;
    *(float4*)(outp + base + tid * 4) = o;
}

// ---------------- launch ----------------
extern "C" void kernel_launch(void* const* d_in, const int* in_sizes, int n_in,
                              void* d_out, int out_size)
{
    const float* inp   = (const float*)d_in[0];
    const int*   amask = (const int*)  d_in[1];
    const float* Wqkv  = (const float*)d_in[2];
    const float* bqkv  = (const float*)d_in[3];
    const float* Wo    = (const float*)d_in[4];
    const float* gamma = (const float*)d_in[5];
    const float* beta  = (const float*)d_in[6];
    float* outp = (float*)d_out;

    float *qkv = nullptr, *attn = nullptr, *yb = nullptr;
    cudaGetSymbolAddress((void**)&qkv,  g_qkv);
    cudaGetSymbolAddress((void**)&attn, g_attn);
    cudaGetSymbolAddress((void**)&yb,   g_y);

    cudaFuncSetAttribute(attn_kernel, cudaFuncAttributeMaxDynamicSharedMemorySize, ATTN_SMEM);

    dim3 blk(256);
    dim3 g1(QKV_N / 128, MROWS / 128);
    gemm_nt_kernel<<<g1, blk>>>(inp, Wqkv, bqkv, qkv, MROWS, QKV_N, DMODEL);

    dim3 g2(S_LEN / 128, NH, BATCH);
    attn_kernel<<<g2, blk, ATTN_SMEM>>>(qkv, amask, attn);

    dim3 g3(DMODEL / 128, MROWS / 128);
    gemm_nt_kernel<<<g3, blk>>>(attn, Wo, nullptr, yb, MROWS, DMODEL, DMODEL);

    ln_kernel<<<MROWS, blk>>>(inp, yb, gamma, beta, outp);
}

// round 12
// speedup vs baseline: 2.8870x; 2.0069x over previous
#include <cuda_runtime.h>
#include <math.h>

// Problem constants
#define S_LEN  2048
#define DMODEL 1024
#define NH     16
#define DHEAD  64
#define BATCH  4
#define MROWS  (BATCH * S_LEN)      // 8192
#define QKV_N  (3 * NH * DHEAD)     // 3072

// Scratch (allocation-free rule: __device__ globals)
__device__ float g_qkv[MROWS * QKV_N];      // 8192 x 3072
__device__ float g_attn[MROWS * DMODEL];    // 8192 x 1024
__device__ float g_y[MROWS * DMODEL];       // 8192 x 1024

// ---------------- tf32 helpers ----------------
__device__ __forceinline__ unsigned int f2tf32(float x) {
    unsigned int r;
    asm("cvt.rna.tf32.f32 %0, %1;" : "=r"(r) : "f"(x));
    return r;
}
__device__ __forceinline__ void mma_tf32(float c[4], const unsigned int a[4],
                                         const unsigned int b[2]) {
    asm("mma.sync.aligned.m16n8k8.row.col.f32.tf32.tf32.f32 "
        "{%0,%1,%2,%3}, {%4,%5,%6,%7}, {%8,%9}, {%0,%1,%2,%3};"
        : "+f"(c[0]), "+f"(c[1]), "+f"(c[2]), "+f"(c[3])
        : "r"(a[0]), "r"(a[1]), "r"(a[2]), "r"(a[3]), "r"(b[0]), "r"(b[1]));
}
__device__ __forceinline__ uint4 cvt4_tf32(float4 v) {
    uint4 r;
    r.x = f2tf32(v.x); r.y = f2tf32(v.y); r.z = f2tf32(v.z); r.w = f2tf32(v.w);
    return r;
}

// ---------------- GEMM (tf32 tensor cores, VALIDATED R11): C = A @ B^T (+bias) --
#define GK 20   // padded k-stride (uints)

__global__ void gemm_nt_kernel(const float* __restrict__ A, const float* __restrict__ B,
                               const float* __restrict__ bias, float* __restrict__ C,
                               int M, int N, int K)
{
    __shared__ unsigned int As[2][128][GK];
    __shared__ unsigned int Bs[2][128][GK];
    const int tid = threadIdx.x;
    const int bm = blockIdx.y * 128, bn = blockIdx.x * 128;
    const int lr = tid >> 2;
    const int lk = (tid & 3) << 2;

    const int wid = tid >> 5;
    const int lane = tid & 31;
    const int warp_m = (wid & 1) * 64;
    const int warp_n = (wid >> 1) * 32;
    const int qr = lane >> 2;
    const int qc = lane & 3;

    const float* Ap = A + (long long)(bm + lr) * K + lk;
    const float* Bp = B + (long long)(bn + lr) * K + lk;
    const long long str64 = (long long)64 * K;

    float c[4][4][4];
#pragma unroll
    for (int i = 0; i < 4; ++i)
#pragma unroll
        for (int j = 0; j < 4; ++j)
#pragma unroll
            for (int r = 0; r < 4; ++r) c[i][j][r] = 0.f;

    float4 pa0 = *(const float4*)(Ap);
    float4 pa1 = *(const float4*)(Ap + str64);
    float4 pb0 = *(const float4*)(Bp);
    float4 pb1 = *(const float4*)(Bp + str64);
    *(uint4*)&As[0][lr][lk]      = cvt4_tf32(pa0);
    *(uint4*)&As[0][lr + 64][lk] = cvt4_tf32(pa1);
    *(uint4*)&Bs[0][lr][lk]      = cvt4_tf32(pb0);
    *(uint4*)&Bs[0][lr + 64][lk] = cvt4_tf32(pb1);
    __syncthreads();

    const int nt_iters = K >> 4;
    for (int t = 0; t < nt_iters; ++t) {
        const int cur = t & 1;
        if (t + 1 < nt_iters) {
            const float* Ax = Ap + (t + 1) * 16;
            const float* Bx = Bp + (t + 1) * 16;
            pa0 = *(const float4*)(Ax); pa1 = *(const float4*)(Ax + str64);
            pb0 = *(const float4*)(Bx); pb1 = *(const float4*)(Bx + str64);
        }
#pragma unroll
        for (int ks = 0; ks < 2; ++ks) {
            const int k0 = ks * 8;
            unsigned int af[4][4];
#pragma unroll
            for (int mt = 0; mt < 4; ++mt) {
                const int row0 = warp_m + mt * 16 + qr;
                af[mt][0] = As[cur][row0    ][k0 + qc];
                af[mt][1] = As[cur][row0 + 8][k0 + qc];
                af[mt][2] = As[cur][row0    ][k0 + qc + 4];
                af[mt][3] = As[cur][row0 + 8][k0 + qc + 4];
            }
            unsigned int bf[4][2];
#pragma unroll
            for (int ntile = 0; ntile < 4; ++ntile) {
                const int col0 = warp_n + ntile * 8 + qr;
                bf[ntile][0] = Bs[cur][col0][k0 + qc];
                bf[ntile][1] = Bs[cur][col0][k0 + qc + 4];
            }
#pragma unroll
            for (int mt = 0; mt < 4; ++mt)
#pragma unroll
                for (int ntile = 0; ntile < 4; ++ntile)
                    mma_tf32(c[mt][ntile], af[mt], bf[ntile]);
        }
        if (t + 1 < nt_iters) {
            const int nx = cur ^ 1;
            *(uint4*)&As[nx][lr][lk]      = cvt4_tf32(pa0);
            *(uint4*)&As[nx][lr + 64][lk] = cvt4_tf32(pa1);
            *(uint4*)&Bs[nx][lr][lk]      = cvt4_tf32(pb0);
            *(uint4*)&Bs[nx][lr + 64][lk] = cvt4_tf32(pb1);
        }
        __syncthreads();
    }

#pragma unroll
    for (int mt = 0; mt < 4; ++mt) {
#pragma unroll
        for (int ntile = 0; ntile < 4; ++ntile) {
            const int row = bm + warp_m + mt * 16 + qr;
            const int col = bn + warp_n + ntile * 8 + 2 * qc;
            float b0 = 0.f, b1 = 0.f;
            if (bias) { b0 = bias[col]; b1 = bias[col + 1]; }
            float2 lo = make_float2(c[mt][ntile][0] + b0, c[mt][ntile][1] + b1);
            float2 hi = make_float2(c[mt][ntile][2] + b0, c[mt][ntile][3] + b1);
            *(float2*)(C + (long long)row * N + col)       = lo;
            *(float2*)(C + (long long)(row + 8) * N + col) = hi;
        }
    }
}

// ---------------- Flash attention (tf32 tensor cores) ----------
// Grid (S/128, H, B), 256 threads = 8 warps; warp w owns q-rows [16w,16w+16).
// S = Q@K^T and O += P@V both via m16n8k8 tf32 mma (fragment maps validated
// by the R11 GEMM pass). Softmax on C fragments; row = 4-lane quad -> shfl 1,2.
// Bank analysis: Qs/Ks/Ps stride 68 (mod32=4): bank=4qr+qc perfect permutation.
//                Vs stride 72 (mod32=8): bank=8qc+qr perfect permutation.
// Ps rows are written AND read only by the owning warp -> __syncwarp suffices.
// Mask is multiplicative (p = exp(.)*mul): exact zeros, all-masked-prefix safe.
#define AQ 68
#define AV 72
#define ATTN_SMEM2 ((128*AQ + 64*AQ + 64*AV + 128*AQ + 64) * 4)   // 105728 B

__global__ void __launch_bounds__(256, 2)
attn_kernel(const float* __restrict__ qkv, const int* __restrict__ amask,
            float* __restrict__ outp)
{
    extern __shared__ unsigned int smu[];
    unsigned int* Qs = smu;                    // [128][AQ] tf32 bits (pre-scaled)
    unsigned int* Ks = Qs + 128 * AQ;          // [64][AQ]
    unsigned int* Vs = Ks + 64 * AQ;           // [64][AV]
    unsigned int* Ps = Vs + 64 * AV;           // [128][AQ]
    float* Msk = (float*)(Ps + 128 * AQ);      // [64]  1=keep, 0=masked

    const int tid = threadIdx.x;
    const int wid = tid >> 5, lane = tid & 31;
    const int qr = lane >> 2, qc = lane & 3;
    const int wrow = wid * 16;
    const int tx = tid & 15, ty = tid >> 4;
    const int q0 = blockIdx.x * 128;
    const int h  = blockIdx.y;
    const int b  = blockIdx.z;

    const float* qbase = qkv + ((long long)(b * S_LEN + q0)) * QKV_N + h * DHEAD;
    const float* kbase = qkv + ((long long)(b * S_LEN)) * QKV_N + NH * DHEAD + h * DHEAD;
    const float* vbase = kbase + NH * DHEAD;
    const int* mrow = amask + b * S_LEN;

    // Q tile: scale by 1/8, convert to tf32 once
#pragma unroll
    for (int it = 0; it < 8; ++it) {
        int r = ty + it * 16;
        int d4 = tx * 4;
        float4 v = *(const float4*)(qbase + (long long)r * QKV_N + d4);
        v.x *= 0.125f; v.y *= 0.125f; v.z *= 0.125f; v.w *= 0.125f;
        *(uint4*)&Qs[r * AQ + d4] = cvt4_tf32(v);
    }

    float m_a = -1e30f, m_b = -1e30f, l_a = 0.f, l_b = 0.f;
    float o[8][4];
#pragma unroll
    for (int nt = 0; nt < 8; ++nt)
#pragma unroll
        for (int r = 0; r < 4; ++r) o[nt][r] = 0.f;

    for (int kt = 0; kt < S_LEN / 64; ++kt) {
        __syncthreads();   // prior consumers of Ks/Vs done (Q load on kt==0)
#pragma unroll
        for (int it = 0; it < 4; ++it) {
            int r = ty + it * 16;
            int d4 = tx * 4;
            float4 kv = *(const float4*)(kbase + (long long)(kt * 64 + r) * QKV_N + d4);
            *(uint4*)&Ks[r * AQ + d4] = cvt4_tf32(kv);
            float4 vv = *(const float4*)(vbase + (long long)(kt * 64 + r) * QKV_N + d4);
            *(uint4*)&Vs[r * AV + d4] = cvt4_tf32(vv);
        }
        if (tid < 64) Msk[tid] = mrow[kt * 64 + tid] ? 0.f : 1.f;
        __syncthreads();

        // ---- S = Q @ K^T ----
        float sc[8][4];
#pragma unroll
        for (int nt = 0; nt < 8; ++nt)
#pragma unroll
            for (int r = 0; r < 4; ++r) sc[nt][r] = 0.f;
#pragma unroll
        for (int ks = 0; ks < 8; ++ks) {
            const int k0 = ks * 8;
            unsigned int af[4];
            af[0] = Qs[(wrow + qr) * AQ + k0 + qc];
            af[1] = Qs[(wrow + qr + 8) * AQ + k0 + qc];
            af[2] = Qs[(wrow + qr) * AQ + k0 + qc + 4];
            af[3] = Qs[(wrow + qr + 8) * AQ + k0 + qc + 4];
#pragma unroll
            for (int nt = 0; nt < 8; ++nt) {
                unsigned int bf[2];
                bf[0] = Ks[(8 * nt + qr) * AQ + k0 + qc];
                bf[1] = Ks[(8 * nt + qr) * AQ + k0 + qc + 4];
                mma_tf32(sc[nt], af, bf);
            }
        }

        // ---- mask + online softmax on fragments ----
        float rmax_a = -1e30f, rmax_b = -1e30f;
#pragma unroll
        for (int nt = 0; nt < 8; ++nt) {
            float mu0 = Msk[8 * nt + 2 * qc];
            float mu1 = Msk[8 * nt + 2 * qc + 1];
            sc[nt][0] = fmaf(sc[nt][0], mu0, (mu0 - 1.f) * 1e30f);
            sc[nt][1] = fmaf(sc[nt][1], mu1, (mu1 - 1.f) * 1e30f);
            sc[nt][2] = fmaf(sc[nt][2], mu0, (mu0 - 1.f) * 1e30f);
            sc[nt][3] = fmaf(sc[nt][3], mu1, (mu1 - 1.f) * 1e30f);
            rmax_a = fmaxf(rmax_a, fmaxf(sc[nt][0], sc[nt][1]));
            rmax_b = fmaxf(rmax_b, fmaxf(sc[nt][2], sc[nt][3]));
        }
        rmax_a = fmaxf(rmax_a, __shfl_xor_sync(0xffffffffu, rmax_a, 1));
        rmax_a = fmaxf(rmax_a, __shfl_xor_sync(0xffffffffu, rmax_a, 2));
        rmax_b = fmaxf(rmax_b, __shfl_xor_sync(0xffffffffu, rmax_b, 1));
        rmax_b = fmaxf(rmax_b, __shfl_xor_sync(0xffffffffu, rmax_b, 2));

        const float mnew_a = fmaxf(m_a, rmax_a);
        const float mnew_b = fmaxf(m_b, rmax_b);
        const float corr_a = __expf(m_a - mnew_a);
        const float corr_b = __expf(m_b - mnew_b);
        m_a = mnew_a; m_b = mnew_b;

        float rs_a = 0.f, rs_b = 0.f;
#pragma unroll
        for (int nt = 0; nt < 8; ++nt) {
            float mu0 = Msk[8 * nt + 2 * qc];
            float mu1 = Msk[8 * nt + 2 * qc + 1];
            float pa0 = __expf(sc[nt][0] - mnew_a) * mu0;
            float pa1 = __expf(sc[nt][1] - mnew_a) * mu1;
            float pb0 = __expf(sc[nt][2] - mnew_b) * mu0;
            float pb1 = __expf(sc[nt][3] - mnew_b) * mu1;
            rs_a += pa0 + pa1;
            rs_b += pb0 + pb1;
            uint2 ua; ua.x = f2tf32(pa0); ua.y = f2tf32(pa1);
            uint2 ub; ub.x = f2tf32(pb0); ub.y = f2tf32(pb1);
            *(uint2*)&Ps[(wrow + qr) * AQ + 8 * nt + 2 * qc]     = ua;
            *(uint2*)&Ps[(wrow + qr + 8) * AQ + 8 * nt + 2 * qc] = ub;
        }
        rs_a += __shfl_xor_sync(0xffffffffu, rs_a, 1);
        rs_a += __shfl_xor_sync(0xffffffffu, rs_a, 2);
        rs_b += __shfl_xor_sync(0xffffffffu, rs_b, 1);
        rs_b += __shfl_xor_sync(0xffffffffu, rs_b, 2);
        l_a = l_a * corr_a + rs_a;
        l_b = l_b * corr_b + rs_b;

#pragma unroll
        for (int nt = 0; nt < 8; ++nt) {
            o[nt][0] *= corr_a; o[nt][1] *= corr_a;
            o[nt][2] *= corr_b; o[nt][3] *= corr_b;
        }
        __syncwarp();   // Ps stores visible to all lanes of this warp

        // ---- O += P @ V ----
#pragma unroll
        for (int ks = 0; ks < 8; ++ks) {
            const int k0 = ks * 8;
            unsigned int af[4];
            af[0] = Ps[(wrow + qr) * AQ + k0 + qc];
            af[1] = Ps[(wrow + qr + 8) * AQ + k0 + qc];
            af[2] = Ps[(wrow + qr) * AQ + k0 + qc + 4];
            af[3] = Ps[(wrow + qr + 8) * AQ + k0 + qc + 4];
#pragma unroll
            for (int nt = 0; nt < 8; ++nt) {
                unsigned int bf[2];
                bf[0] = Vs[(k0 + qc) * AV + 8 * nt + qr];
                bf[1] = Vs[(k0 + qc + 4) * AV + 8 * nt + qr];
                mma_tf32(o[nt], af, bf);
            }
        }
    }

    // Normalize and write [row][h*64 + col]
    const float inv_a = 1.0f / l_a;
    const float inv_b = 1.0f / l_b;
    const long long rowa = (long long)(b * S_LEN + q0 + wrow + qr);
    const long long rowb = rowa + 8;
#pragma unroll
    for (int nt = 0; nt < 8; ++nt) {
        const int col = h * DHEAD + 8 * nt + 2 * qc;
        *(float2*)(outp + rowa * DMODEL + col) = make_float2(o[nt][0] * inv_a, o[nt][1] * inv_a);
        *(float2*)(outp + rowb * DMODEL + col) = make_float2(o[nt][2] * inv_b, o[nt][3] * inv_b);
    }
}

// ---------------- Residual + LayerNorm ----------------
__global__ void ln_kernel(const float* __restrict__ x0, const float* __restrict__ y,
                          const float* __restrict__ gamma, const float* __restrict__ beta,
                          float* __restrict__ outp)
{
    const int row = blockIdx.x;
    const int tid = threadIdx.x;
    const long long base = (long long)row * DMODEL;
    float4 xv = *(const float4*)(x0 + base + tid * 4);
    float4 yv = *(const float4*)(y + base + tid * 4);
    float v0 = xv.x + yv.x, v1 = xv.y + yv.y, v2 = xv.z + yv.z, v3 = xv.w + yv.w;
    float s = v0 + v1 + v2 + v3;
    float q = v0 * v0 + v1 * v1 + v2 * v2 + v3 * v3;
#pragma unroll
    for (int off = 16; off > 0; off >>= 1) {
        s += __shfl_xor_sync(0xffffffffu, s, off);
        q += __shfl_xor_sync(0xffffffffu, q, off);
    }
    __shared__ float reds[8], redq[8];
    const int wid = tid >> 5, lane = tid & 31;
    if (lane == 0) { reds[wid] = s; redq[wid] = q; }
    __syncthreads();
    float ts = 0.f, tq = 0.f;
#pragma unroll
    for (int w = 0; w < 8; ++w) { ts += reds[w]; tq += redq[w]; }
    const float mu   = ts * (1.0f / DMODEL);
    const float var  = tq * (1.0f / DMODEL) - mu * mu;
    const float rstd = rsqrtf(var + 1e-5f);
    float4 gv = *(const float4*)(gamma + tid * 4);
    float4 bv = *(const float4*)(beta + tid * 4);
    float4 outv;
    outv.x = (v0 - mu) * rstd * gv.x + bv.x;
    outv.y = (v1 - mu) * rstd * gv.y + bv.y;
    outv.z = (v2 - mu) * rstd * gv.z + bv.z;
    outv.w = (v3 - mu) * rstd * gv.w + bv.w;
    *(float4*)(outp + base + tid * 4) = outv;
}

// ---------------- launch ----------------
extern "C" void kernel_launch(void* const* d_in, const int* in_sizes, int n_in,
                              void* d_out, int out_size)
{
    const float* inp   = (const float*)d_in[0];
    const int*   amask = (const int*)  d_in[1];
    const float* Wqkv  = (const float*)d_in[2];
    const float* bqkv  = (const float*)d_in[3];
    const float* Wo    = (const float*)d_in[4];
    const float* gamma = (const float*)d_in[5];
    const float* beta  = (const float*)d_in[6];
    float* outp = (float*)d_out;

    float *qkv = nullptr, *attn = nullptr, *yb = nullptr;
    cudaGetSymbolAddress((void**)&qkv,  g_qkv);
    cudaGetSymbolAddress((void**)&attn, g_attn);
    cudaGetSymbolAddress((void**)&yb,   g_y);

    cudaFuncSetAttribute(attn_kernel, cudaFuncAttributeMaxDynamicSharedMemorySize, ATTN_SMEM2);

    dim3 blk(256);
    dim3 g1(QKV_N / 128, MROWS / 128);
    gemm_nt_kernel<<<g1, blk>>>(inp, Wqkv, bqkv, qkv, MROWS, QKV_N, DMODEL);

    dim3 g2(S_LEN / 128, NH, BATCH);
    attn_kernel<<<g2, blk, ATTN_SMEM2>>>(qkv, amask, attn);

    dim3 g3(DMODEL / 128, MROWS / 128);
    gemm_nt_kernel<<<g3, blk>>>(attn, Wo, nullptr, yb, MROWS, DMODEL, DMODEL);

    ln_kernel<<<MROWS, blk>>>(inp, yb, gamma, beta, outp);
}